// round 4
// baseline (speedup 1.0000x reference)
#include <cuda_runtime.h>
#include <math.h>

#define NN 10000
#define EE 160000
#define DD 128
#define HH 4
#define HC 512
#define RSQRT_D 0.08838834764831845f  // 1/sqrt(128)

// ---------------- scratch (device globals; no runtime allocation) -----------
__device__ float g_q[NN * HC];
__device__ float g_k[NN * HC];
__device__ float g_v[NN * HC];
__device__ float g_skip[NN * HC];
__device__ float g_qWe[NN * HC];   // qWe[n,h*128+c] = sum_d We[c,h*128+d]*q[n,h*128+d]
__device__ float g_qbe[NN * HH];
__device__ float g_ex[EE * HH];    // exp(alpha)
__device__ float g_aggv[NN * HC];  // sum attn * v[src]
__device__ float g_t[NN * HC];     // sum attn * edge_attr
__device__ float g_agge[NN * HC];  // t @ We (+ gated be)
__device__ float g_normed[NN * HC];
__device__ int   g_count[NN];
__device__ int   g_off[NN];
__device__ int   g_cur[NN];
__device__ int   g_elist[EE];
__device__ int   g_esrc[EE];
__device__ int   g_is64;

// ---- edge-index accessor: dtype decided at runtime, indices clamped --------
__device__ __forceinline__ int load_idx(const void* ei, int is64, long long pos) {
    int v = is64 ? (int)((const long long*)ei)[pos] : ((const int*)ei)[pos];
    return min(max(v, 0), NN - 1);
}

// int64 little-endian values < 2^31 have all-zero odd 32-bit words.
__global__ void detect_kernel(const void* ei) {
    if (threadIdx.x == 0 && blockIdx.x == 0) {
        const int* p = (const int*)ei;
        int orv = 0;
        for (int i = 1; i < 2048; i += 2) orv |= p[i];
        g_is64 = (orv == 0) ? 1 : 0;
    }
}

__global__ void zero_kernel() {
    int t = blockIdx.x * 256 + threadIdx.x;
    if (t < NN) g_count[t] = 0;
}

// ---------------- GEMM: C[M,NC] = A[M,K] @ W[K,NC] + bias -------------------
// SEL 0..3: A = x (K=128), C = g_q/g_k/g_v/g_skip, NC=512
// SEL 4:    A = g_t head slice (K=128), C = g_agge, NC=512, bias gated by count>0
// SEL 5:    A = g_normed (K=512), C = d_out, NC=128, epilogue elu(acc+b+xres)
template <int K, int SEL>
__global__ __launch_bounds__(256) void gemm_kernel(
    const float* __restrict__ A_in, const float* __restrict__ W,
    const float* __restrict__ bias, const float* __restrict__ xres,
    float* __restrict__ Cout) {
    const int M = NN, NC = (SEL == 5) ? DD : HC;
    float* C = (SEL == 0) ? g_q : (SEL == 1) ? g_k : (SEL == 2) ? g_v
             : (SEL == 3) ? g_skip : (SEL == 4) ? g_agge : Cout;

    __shared__ float As[32][33];
    int row0 = blockIdx.x * 32;
    int col  = blockIdx.y * 64 + (threadIdx.x & 63);
    int rsub = threadIdx.x >> 6;
    int hofs = (SEL == 4) ? ((blockIdx.y * 64) >> 7) * 128 : 0;

    float acc[8];
#pragma unroll
    for (int j = 0; j < 8; j++) acc[j] = 0.f;

    for (int kb = 0; kb < K; kb += 32) {
        __syncthreads();
#pragma unroll
        for (int i = 0; i < 4; i++) {
            int idx = threadIdx.x + i * 256;
            int r = idx >> 5, kc = idx & 31;
            int gr = row0 + r;
            float av = 0.f;
            if (gr < M) {
                if (SEL == 4)      av = g_t[gr * HC + hofs + kb + kc];
                else if (SEL == 5) av = g_normed[gr * HC + kb + kc];
                else               av = A_in[gr * K + kb + kc];
            }
            As[r][kc] = av;
        }
        __syncthreads();
#pragma unroll
        for (int kc = 0; kc < 32; kc++) {
            float w = W[(kb + kc) * NC + col];
#pragma unroll
            for (int j = 0; j < 8; j++) acc[j] += As[rsub + j * 4][kc] * w;
        }
    }
    float b = bias[col];
#pragma unroll
    for (int j = 0; j < 8; j++) {
        int r = row0 + rsub + j * 4;
        if (r < M) {
            float o;
            if (SEL == 4) o = acc[j] + ((g_count[r] > 0) ? b : 0.f);
            else          o = acc[j] + b;
            if (SEL == 5) {
                o += xres[r * NC + col];
                o = (o > 0.f) ? o : expm1f(o);
            }
            C[r * NC + col] = o;
        }
    }
}

// ---------------- qWe + qbe: per head h, qWe = q_h @ We_h^T ------------------
__global__ __launch_bounds__(256) void qwe_kernel(
    const float* __restrict__ We, const float* __restrict__ be) {
    __shared__ float qs[32][128];
    __shared__ float Ws[32][128];
    int n0 = blockIdx.x * 32;
    int h  = blockIdx.y;
    int tid = threadIdx.x;

#pragma unroll
    for (int i = 0; i < 16; i++) {
        int lin = tid + i * 256;
        int r = lin >> 7, c = lin & 127;
        int gr = n0 + r;
        qs[r][c] = (gr < NN) ? g_q[gr * HC + h * 128 + c] : 0.f;
    }

    float acc[16];
#pragma unroll
    for (int j = 0; j < 16; j++) acc[j] = 0.f;
    int c = tid & 127, r0 = (tid >> 7) * 16;

    for (int db = 0; db < 128; db += 32) {
        __syncthreads();
#pragma unroll
        for (int i = 0; i < 16; i++) {
            int lin = tid + i * 256;
            int cc = lin >> 5, dd = lin & 31;
            Ws[dd][cc] = We[cc * HC + h * 128 + db + dd];
        }
        __syncthreads();
#pragma unroll
        for (int dd = 0; dd < 32; dd++) {
            float w = Ws[dd][c];
#pragma unroll
            for (int j = 0; j < 16; j++) acc[j] += qs[r0 + j][db + dd] * w;
        }
    }
#pragma unroll
    for (int j = 0; j < 16; j++) {
        int gr = n0 + r0 + j;
        if (gr < NN) g_qWe[gr * HC + h * 128 + c] = acc[j];
    }
    __syncthreads();
    if (tid < 32) {
        int gr = n0 + tid;
        if (gr < NN) {
            float s = 0.f;
            for (int d = 0; d < 128; d++) s += qs[tid][d] * be[h * 128 + d];
            g_qbe[gr * HH + h] = s;
        }
    }
}

// ---------------- CSR build (int atomics only, in-bounds by clamp) -----------
__global__ void hist_kernel(const void* __restrict__ ei) {
    int t = blockIdx.x * 256 + threadIdx.x;
    if (t < EE) {
        int d = load_idx(ei, g_is64, (long long)EE + t);
        atomicAdd(&g_count[d], 1);
    }
}

__global__ __launch_bounds__(1024) void scan_kernel() {
    __shared__ int sh[1024];
    int t = threadIdx.x;
    int loc[16];
    int s = 0;
#pragma unroll
    for (int i = 0; i < 16; i++) {
        int idx = t * 16 + i;
        int cv = (idx < NN) ? g_count[idx] : 0;
        loc[i] = cv; s += cv;
    }
    sh[t] = s;
    __syncthreads();
    for (int off = 1; off < 1024; off <<= 1) {
        int v = (t >= off) ? sh[t - off] : 0;
        __syncthreads();
        sh[t] += v;
        __syncthreads();
    }
    int excl = sh[t] - s;
#pragma unroll
    for (int i = 0; i < 16; i++) {
        int idx = t * 16 + i;
        if (idx < NN) {
            g_off[idx] = excl;
            g_cur[idx] = excl;
            excl += loc[i];
        }
    }
}

__global__ void fill_kernel(const void* __restrict__ ei) {
    int t = blockIdx.x * 256 + threadIdx.x;
    if (t < EE) {
        int is64 = g_is64;
        int d = load_idx(ei, is64, (long long)EE + t);
        int pos = atomicAdd(&g_cur[d], 1);
        pos = min(max(pos, 0), EE - 1);
        g_elist[pos] = t;
        g_esrc[pos]  = load_idx(ei, is64, t);
    }
}

// ---------------- edge pass: alpha -> exp (no atomics) -----------------------
// block = 256 threads = 2 edges x 128 lanes
__global__ __launch_bounds__(256) void edge_alpha_kernel(
    const float* __restrict__ ea, const void* __restrict__ ei) {
    __shared__ float red[8][4];
    int tid = threadIdx.x;
    int e = blockIdx.x * 2 + (tid >> 7);
    int l = tid & 127;
    int w = tid >> 5;
    int is64 = g_is64;

    float p[4] = {0.f, 0.f, 0.f, 0.f};
    int d = 0;
    if (e < EE) {
        int s = load_idx(ei, is64, e);
        d = load_idx(ei, is64, (long long)EE + e);
        float eav = ea[e * DD + l];
#pragma unroll
        for (int h = 0; h < 4; h++) {
            int o = h * 128 + l;
            p[h] = g_q[d * HC + o] * g_k[s * HC + o] + eav * g_qWe[d * HC + o];
        }
    }
#pragma unroll
    for (int h = 0; h < 4; h++) {
#pragma unroll
        for (int off = 16; off > 0; off >>= 1)
            p[h] += __shfl_xor_sync(0xffffffffu, p[h], off);
    }
    if ((tid & 31) == 0) {
#pragma unroll
        for (int h = 0; h < 4; h++) red[w][h] = p[h];
    }
    __syncthreads();
    if (tid < 8) {
        int slot = tid >> 2, h = tid & 3;
        int e2 = blockIdx.x * 2 + slot;
        if (e2 < EE) {
            float a = red[slot * 4 + 0][h] + red[slot * 4 + 1][h]
                    + red[slot * 4 + 2][h] + red[slot * 4 + 3][h];
            int d2 = load_idx(ei, is64, (long long)EE + e2);
            a = (a + g_qbe[d2 * HH + h]) * RSQRT_D;
            // no max-subtraction: |alpha| <~ 8 over all edges -> fp32-safe;
            // attn = ex/sum(ex) is mathematically identical to the reference
            g_ex[e2 * HH + h] = expf(a);
        }
    }
}

// ---------------- CSR aggregate: block per dst node, denom inline ------------
__global__ __launch_bounds__(128) void csr_agg_kernel(const float* __restrict__ ea) {
    int n = blockIdx.x;
    int l = threadIdx.x;
    int off = g_off[n];
    int cnt = g_count[n];

    float accv[4] = {0.f, 0.f, 0.f, 0.f};
    float acct[4] = {0.f, 0.f, 0.f, 0.f};

    if (cnt > 0) {
        float den[4] = {0.f, 0.f, 0.f, 0.f};
        for (int k = 0; k < cnt; k++) {
            int eid = g_elist[off + k];
#pragma unroll
            for (int h = 0; h < 4; h++) den[h] += g_ex[eid * HH + h];
        }
        float rden[4];
#pragma unroll
        for (int h = 0; h < 4; h++) rden[h] = 1.f / den[h];

        for (int k = 0; k < cnt; k++) {
            int eid = g_elist[off + k];
            int s   = g_esrc[off + k];
            float eav = ea[eid * DD + l];
#pragma unroll
            for (int h = 0; h < 4; h++) {
                float at = g_ex[eid * HH + h] * rden[h];
                accv[h] += at * g_v[s * HC + h * 128 + l];
                acct[h] += at * eav;
            }
        }
    }
#pragma unroll
    for (int h = 0; h < 4; h++) {
        g_aggv[n * HC + h * 128 + l] = accv[h];
        g_t[n * HC + h * 128 + l]   = acct[h];
    }
}

// ---------------- LayerNorm over HC=512 (aggv + agge + skip) -----------------
__global__ __launch_bounds__(128) void ln_kernel(
    const float* __restrict__ g, const float* __restrict__ b) {
    int n = blockIdx.x;
    int tid = threadIdx.x;
    float vals[4];
    float s = 0.f, s2 = 0.f;
#pragma unroll
    for (int j = 0; j < 4; j++) {
        int c = tid + j * 128;
        float o = g_aggv[n * HC + c] + g_agge[n * HC + c] + g_skip[n * HC + c];
        vals[j] = o; s += o; s2 += o * o;
    }
    __shared__ float sh[8];
#pragma unroll
    for (int off = 16; off > 0; off >>= 1) {
        s  += __shfl_xor_sync(0xffffffffu, s, off);
        s2 += __shfl_xor_sync(0xffffffffu, s2, off);
    }
    int wid = tid >> 5, lane = tid & 31;
    if (lane == 0) { sh[wid] = s; sh[4 + wid] = s2; }
    __syncthreads();
    s  = sh[0] + sh[1] + sh[2] + sh[3];
    s2 = sh[4] + sh[5] + sh[6] + sh[7];
    float mu = s * (1.f / 512.f);
    float var = s2 * (1.f / 512.f) - mu * mu;
    float rs = rsqrtf(var + 1e-5f);
#pragma unroll
    for (int j = 0; j < 4; j++) {
        int c = tid + j * 128;
        g_normed[n * HC + c] = (vals[j] - mu) * rs * g[c] + b[c];
    }
}

// ---------------- launch -----------------------------------------------------
extern "C" void kernel_launch(void* const* d_in, const int* in_sizes, int n_in,
                              void* d_out, int out_size) {
    const float* x     = (const float*)d_in[0];
    const void*  ei    = d_in[1];                 // int32 or int64, sniffed on device
    const float* ea    = (const float*)d_in[2];
    const float* Wq    = (const float*)d_in[3];
    const float* bq    = (const float*)d_in[4];
    const float* Wk    = (const float*)d_in[5];
    const float* bk    = (const float*)d_in[6];
    const float* Wv    = (const float*)d_in[7];
    const float* bv    = (const float*)d_in[8];
    const float* We    = (const float*)d_in[9];
    const float* be    = (const float*)d_in[10];
    const float* Wskip = (const float*)d_in[11];
    const float* bskip = (const float*)d_in[12];
    const float* ln_g  = (const float*)d_in[13];
    const float* ln_b  = (const float*)d_in[14];
    const float* Wlin  = (const float*)d_in[15];
    const float* blin  = (const float*)d_in[16];

    detect_kernel<<<1, 32>>>(ei);
    zero_kernel<<<(NN + 255) / 256, 256>>>();

    dim3 gA((NN + 31) / 32, HC / 64);
    gemm_kernel<DD, 0><<<gA, 256>>>(x, Wq, bq, nullptr, nullptr);
    gemm_kernel<DD, 1><<<gA, 256>>>(x, Wk, bk, nullptr, nullptr);
    gemm_kernel<DD, 2><<<gA, 256>>>(x, Wv, bv, nullptr, nullptr);
    gemm_kernel<DD, 3><<<gA, 256>>>(x, Wskip, bskip, nullptr, nullptr);

    dim3 gQ((NN + 31) / 32, HH);
    qwe_kernel<<<gQ, 256>>>(We, be);

    hist_kernel<<<(EE + 255) / 256, 256>>>(ei);
    scan_kernel<<<1, 1024>>>();
    fill_kernel<<<(EE + 255) / 256, 256>>>(ei);

    edge_alpha_kernel<<<(EE + 1) / 2, 256>>>(ea, ei);

    csr_agg_kernel<<<NN, 128>>>(ea);

    gemm_kernel<DD, 4><<<gA, 256>>>(nullptr, We, be, nullptr, nullptr);

    ln_kernel<<<NN, 128>>>(ln_g, ln_b);

    dim3 gF((NN + 31) / 32, DD / 64);
    gemm_kernel<HC, 5><<<gF, 256>>>(nullptr, Wlin, blin, x, (float*)d_out);
}

// round 5
// speedup vs baseline: 2.2943x; 2.2943x over previous
#include <cuda_runtime.h>
#include <math.h>

#define NN 10000
#define EE 160000
#define DD 128
#define HH 4
#define HC 512
#define STRD 2564            // fused node-feature stride: q|k|v|skip|qWe|qbe
#define QOFF 0
#define KOFF 512
#define VOFF 1024
#define SKOFF 1536
#define QWEOFF 2048
#define QBEOFF 2560
#define RSQRT_D 0.08838834764831845f  // 1/sqrt(128)

// ---------------- scratch (device globals; no runtime allocation) -----------
__device__ float g_nodes[NN * STRD];   // fused per-node features
__device__ float g_Wcat[DD * STRD];    // concatenated weights
__device__ float g_bcat[STRD];         // concatenated bias
__device__ float g_ex[EE * HH];        // exp(alpha)
__device__ float g_aggv[NN * HC];      // sum attn * v[src]
__device__ float g_t[NN * HC];         // sum attn * edge_attr
__device__ float g_agge[NN * HC];      // t @ We (+ gated be)
__device__ float g_normed[NN * HC];
__device__ int   g_count[NN];
__device__ int   g_off[NN];
__device__ int   g_cur[NN];
__device__ int   g_elist[EE];
__device__ int   g_esrc[EE];
__device__ int   g_is64;

// ---- edge-index accessor: dtype decided at runtime, indices clamped --------
__device__ __forceinline__ int load_idx(const void* ei, int is64, long long pos) {
    int v = is64 ? (int)((const long long*)ei)[pos] : ((const int*)ei)[pos];
    return min(max(v, 0), NN - 1);
}

__global__ void detect_kernel(const void* ei) {
    if (threadIdx.x == 0 && blockIdx.x == 0) {
        const int* p = (const int*)ei;
        int orv = 0;
        for (int i = 1; i < 2048; i += 2) orv |= p[i];
        g_is64 = (orv == 0) ? 1 : 0;
    }
}

__global__ void zero_kernel() {
    int t = blockIdx.x * 256 + threadIdx.x;
    if (t < NN) g_count[t] = 0;
}

// ---------------- weight prep: build Wcat / bcat -----------------------------
// cols 0..511: Wq|bq   512..1023: Wk|bk   1024..1535: Wv|bv   1536..2047: Wskip
// cols 2048..2559: Wqe_h[t,m] = sum_d Wq[t,h*128+d]*We[m,h*128+d]
// cols 2560..2563: wqbe_h[t] = sum_d Wq[t,h*128+d]*be[h*128+d]
__global__ __launch_bounds__(128) void prep_kernel(
    const float* __restrict__ Wq, const float* __restrict__ bq,
    const float* __restrict__ Wk, const float* __restrict__ bk,
    const float* __restrict__ Wv, const float* __restrict__ bv,
    const float* __restrict__ We, const float* __restrict__ be,
    const float* __restrict__ Wskip, const float* __restrict__ bskip) {
    int c = blockIdx.x, t = threadIdx.x;
    __shared__ float wrow[128];
    float val, bias = 0.f;
    if (c < 512)       { val = Wq[t * HC + c];            bias = bq[c]; }
    else if (c < 1024) { val = Wk[t * HC + c - 512];      bias = bk[c - 512]; }
    else if (c < 1536) { val = Wv[t * HC + c - 1024];     bias = bv[c - 1024]; }
    else if (c < 2048) { val = Wskip[t * HC + c - 1536];  bias = bskip[c - 1536]; }
    else if (c < 2560) {
        int cc = c - 2048, h = cc >> 7, m = cc & 127;
        wrow[t] = We[m * HC + h * 128 + t];
        __syncthreads();
        float acc = 0.f;
        for (int d = 0; d < 128; d++) acc += Wq[t * HC + h * 128 + d] * wrow[d];
        val = acc;
        if (t == 0) {
            float bacc = 0.f;
            for (int d = 0; d < 128; d++) bacc += bq[h * 128 + d] * wrow[d];
            bias = bacc;
        }
    } else {
        int h = c - 2560;
        float acc = 0.f;
        for (int d = 0; d < 128; d++) acc += Wq[t * HC + h * 128 + d] * be[h * 128 + d];
        val = acc;
        if (t == 0) {
            float bacc = 0.f;
            for (int d = 0; d < 128; d++) bacc += bq[h * 128 + d] * be[h * 128 + d];
            bias = bacc;
        }
    }
    g_Wcat[t * STRD + c] = val;
    if (t == 0) g_bcat[c] = bias;
}

// ---------------- register-blocked SGEMM (128x128 tile, 8x8/thread) ----------
// SEL 0: C[NN,2564] = x[NN,128] @ Wcat + bcat            -> g_nodes
// SEL 4: per head h=by: g_agge[:,h*128+n] = g_t[:,h*128+:] @ We[:,h*128+n] + gated be
// SEL 5: d_out = elu(g_normed[NN,512] @ Wlin[512,128] + blin + x)
template <int SEL>
__global__ __launch_bounds__(256, 2) void sgemm_kernel(
    const float* __restrict__ Ain, const float* __restrict__ Bin,
    const float* __restrict__ biasin, const float* __restrict__ xres,
    float* __restrict__ Cout) {
    constexpr int K    = (SEL == 5) ? 512 : 128;
    constexpr int NTOT = (SEL == 0) ? STRD : (SEL == 4) ? HC : DD;
    constexpr int BS   = NTOT;  // B row stride == C row stride == total cols
    const float* A = (SEL == 0) ? Ain : (SEL == 4) ? g_t : g_normed;
    const float* B = (SEL == 0) ? g_Wcat : Bin;
    const float* bias_p = (SEL == 0) ? g_bcat : biasin;
    float* C = (SEL == 0) ? g_nodes : (SEL == 4) ? g_agge : Cout;
    constexpr int ASTR = (SEL == 0) ? DD : HC;

    __shared__ float As[16][132];
    __shared__ float Bs[16][132];

    int tid = threadIdx.x;
    int row0 = blockIdx.x * 128;
    int col0 = blockIdx.y * 128;
    int tx = tid & 15, ty = tid >> 4;
    const int acb = (SEL == 4) ? col0 : 0;  // head slice of g_t

    float acc[8][8];
#pragma unroll
    for (int i = 0; i < 8; i++)
#pragma unroll
        for (int j = 0; j < 8; j++) acc[i][j] = 0.f;

    for (int kb = 0; kb < K; kb += 16) {
        __syncthreads();
#pragma unroll
        for (int i = 0; i < 2; i++) {
            int idx = tid + i * 256;
            int m = idx >> 2, kq = idx & 3;
            int r = row0 + m;
            float4 av = make_float4(0.f, 0.f, 0.f, 0.f);
            if (r < NN) av = *(const float4*)&A[r * ASTR + acb + kb + kq * 4];
            As[kq * 4 + 0][m] = av.x; As[kq * 4 + 1][m] = av.y;
            As[kq * 4 + 2][m] = av.z; As[kq * 4 + 3][m] = av.w;
        }
#pragma unroll
        for (int i = 0; i < 2; i++) {
            int idx = tid + i * 256;
            int kc = idx >> 5, n4 = idx & 31;
            int cg = col0 + n4 * 4;
            float4 bv = make_float4(0.f, 0.f, 0.f, 0.f);
            if (cg < NTOT) bv = *(const float4*)&B[(kb + kc) * BS + cg];
            *(float4*)&Bs[kc][n4 * 4] = bv;
        }
        __syncthreads();
#pragma unroll
        for (int kc = 0; kc < 16; kc++) {
            float a[8], b[8];
            *(float4*)&a[0] = *(const float4*)&As[kc][ty * 8];
            *(float4*)&a[4] = *(const float4*)&As[kc][ty * 8 + 4];
            *(float4*)&b[0] = *(const float4*)&Bs[kc][tx * 8];
            *(float4*)&b[4] = *(const float4*)&Bs[kc][tx * 8 + 4];
#pragma unroll
            for (int i = 0; i < 8; i++)
#pragma unroll
                for (int j = 0; j < 8; j++) acc[i][j] += a[i] * b[j];
        }
    }

    float bias[8];
#pragma unroll
    for (int j = 0; j < 8; j++) {
        int c = col0 + tx * 8 + j;
        bias[j] = (c < NTOT) ? bias_p[c] : 0.f;
    }
#pragma unroll
    for (int i = 0; i < 8; i++) {
        int r = row0 + ty * 8 + i;
        if (r >= NN) continue;
        float gate = 1.f;
        if (SEL == 4) gate = (g_count[r] > 0) ? 1.f : 0.f;
        float out[8];
#pragma unroll
        for (int j = 0; j < 8; j++) {
            float o = acc[i][j] + ((SEL == 4) ? gate * bias[j] : bias[j]);
            if (SEL == 5) {
                o += xres[r * DD + col0 + tx * 8 + j];
                o = (o > 0.f) ? o : expm1f(o);
            }
            out[j] = o;
        }
        int c = col0 + tx * 8;
        if (c < NTOT)     *(float4*)&C[r * BS + c]     = *(float4*)&out[0];
        if (c + 4 < NTOT) *(float4*)&C[r * BS + c + 4] = *(float4*)&out[4];
    }
}

// ---------------- CSR build (int atomics only, in-bounds by clamp) -----------
__global__ void hist_kernel(const void* __restrict__ ei) {
    int t = blockIdx.x * 256 + threadIdx.x;
    if (t < EE) {
        int d = load_idx(ei, g_is64, (long long)EE + t);
        atomicAdd(&g_count[d], 1);
    }
}

__global__ __launch_bounds__(1024) void scan_kernel() {
    __shared__ int sh[1024];
    int t = threadIdx.x;
    int loc[16];
    int s = 0;
#pragma unroll
    for (int i = 0; i < 16; i++) {
        int idx = t * 16 + i;
        int cv = (idx < NN) ? g_count[idx] : 0;
        loc[i] = cv; s += cv;
    }
    sh[t] = s;
    __syncthreads();
    for (int off = 1; off < 1024; off <<= 1) {
        int v = (t >= off) ? sh[t - off] : 0;
        __syncthreads();
        sh[t] += v;
        __syncthreads();
    }
    int excl = sh[t] - s;
#pragma unroll
    for (int i = 0; i < 16; i++) {
        int idx = t * 16 + i;
        if (idx < NN) {
            g_off[idx] = excl;
            g_cur[idx] = excl;
            excl += loc[i];
        }
    }
}

__global__ void fill_kernel(const void* __restrict__ ei) {
    int t = blockIdx.x * 256 + threadIdx.x;
    if (t < EE) {
        int is64 = g_is64;
        int d = load_idx(ei, is64, (long long)EE + t);
        int pos = atomicAdd(&g_cur[d], 1);
        pos = min(max(pos, 0), EE - 1);
        g_elist[pos] = t;
        g_esrc[pos]  = load_idx(ei, is64, t);
    }
}

// ---------------- edge pass: alpha -> exp (no atomics) -----------------------
// block = 256 threads = 2 edges x 128 lanes
__global__ __launch_bounds__(256) void edge_alpha_kernel(
    const float* __restrict__ ea, const void* __restrict__ ei) {
    __shared__ float red[8][4];
    int tid = threadIdx.x;
    int e = blockIdx.x * 2 + (tid >> 7);
    int l = tid & 127;
    int w = tid >> 5;
    int is64 = g_is64;

    float p[4] = {0.f, 0.f, 0.f, 0.f};
    if (e < EE) {
        int s = load_idx(ei, is64, e);
        int d = load_idx(ei, is64, (long long)EE + e);
        float eav = ea[e * DD + l];
#pragma unroll
        for (int h = 0; h < 4; h++) {
            int o = h * 128 + l;
            p[h] = g_nodes[d * STRD + QOFF + o] * g_nodes[s * STRD + KOFF + o]
                 + eav * g_nodes[d * STRD + QWEOFF + o];
        }
    }
#pragma unroll
    for (int h = 0; h < 4; h++) {
#pragma unroll
        for (int off = 16; off > 0; off >>= 1)
            p[h] += __shfl_xor_sync(0xffffffffu, p[h], off);
    }
    if ((tid & 31) == 0) {
#pragma unroll
        for (int h = 0; h < 4; h++) red[w][h] = p[h];
    }
    __syncthreads();
    if (tid < 8) {
        int slot = tid >> 2, h = tid & 3;
        int e2 = blockIdx.x * 2 + slot;
        if (e2 < EE) {
            float a = red[slot * 4 + 0][h] + red[slot * 4 + 1][h]
                    + red[slot * 4 + 2][h] + red[slot * 4 + 3][h];
            int d2 = load_idx(ei, is64, (long long)EE + e2);
            a = (a + g_nodes[d2 * STRD + QBEOFF + h]) * RSQRT_D;
            // no max-subtraction: |alpha| <~ 8 over all edges -> fp32-safe;
            // attn = ex/sum(ex) is mathematically identical to the reference
            g_ex[e2 * HH + h] = expf(a);
        }
    }
}

// ---------------- CSR aggregate: block per dst node, denom inline ------------
__global__ __launch_bounds__(128) void csr_agg_kernel(const float* __restrict__ ea) {
    int n = blockIdx.x;
    int l = threadIdx.x;
    int off = g_off[n];
    int cnt = g_count[n];

    float accv[4] = {0.f, 0.f, 0.f, 0.f};
    float acct[4] = {0.f, 0.f, 0.f, 0.f};

    if (cnt > 0) {
        float den[4] = {0.f, 0.f, 0.f, 0.f};
        for (int k = 0; k < cnt; k++) {
            int eid = g_elist[off + k];
#pragma unroll
            for (int h = 0; h < 4; h++) den[h] += g_ex[eid * HH + h];
        }
        float rden[4];
#pragma unroll
        for (int h = 0; h < 4; h++) rden[h] = 1.f / den[h];

        for (int k = 0; k < cnt; k++) {
            int eid = g_elist[off + k];
            int s   = g_esrc[off + k];
            float eav = ea[eid * DD + l];
#pragma unroll
            for (int h = 0; h < 4; h++) {
                float at = g_ex[eid * HH + h] * rden[h];
                accv[h] += at * g_nodes[s * STRD + VOFF + h * 128 + l];
                acct[h] += at * eav;
            }
        }
    }
#pragma unroll
    for (int h = 0; h < 4; h++) {
        g_aggv[n * HC + h * 128 + l] = accv[h];
        g_t[n * HC + h * 128 + l]   = acct[h];
    }
}

// ---------------- LayerNorm over HC=512 (aggv + agge + skip) -----------------
__global__ __launch_bounds__(128) void ln_kernel(
    const float* __restrict__ g, const float* __restrict__ b) {
    int n = blockIdx.x;
    int tid = threadIdx.x;
    float vals[4];
    float s = 0.f, s2 = 0.f;
#pragma unroll
    for (int j = 0; j < 4; j++) {
        int c = tid + j * 128;
        float o = g_aggv[n * HC + c] + g_agge[n * HC + c]
                + g_nodes[n * STRD + SKOFF + c];
        vals[j] = o; s += o; s2 += o * o;
    }
    __shared__ float sh[8];
#pragma unroll
    for (int off = 16; off > 0; off >>= 1) {
        s  += __shfl_xor_sync(0xffffffffu, s, off);
        s2 += __shfl_xor_sync(0xffffffffu, s2, off);
    }
    int wid = tid >> 5, lane = tid & 31;
    if (lane == 0) { sh[wid] = s; sh[4 + wid] = s2; }
    __syncthreads();
    s  = sh[0] + sh[1] + sh[2] + sh[3];
    s2 = sh[4] + sh[5] + sh[6] + sh[7];
    float mu = s * (1.f / 512.f);
    float var = s2 * (1.f / 512.f) - mu * mu;
    float rs = rsqrtf(var + 1e-5f);
#pragma unroll
    for (int j = 0; j < 4; j++) {
        int c = tid + j * 128;
        g_normed[n * HC + c] = (vals[j] - mu) * rs * g[c] + b[c];
    }
}

// ---------------- launch -----------------------------------------------------
extern "C" void kernel_launch(void* const* d_in, const int* in_sizes, int n_in,
                              void* d_out, int out_size) {
    const float* x     = (const float*)d_in[0];
    const void*  ei    = d_in[1];
    const float* ea    = (const float*)d_in[2];
    const float* Wq    = (const float*)d_in[3];
    const float* bq    = (const float*)d_in[4];
    const float* Wk    = (const float*)d_in[5];
    const float* bk    = (const float*)d_in[6];
    const float* Wv    = (const float*)d_in[7];
    const float* bv    = (const float*)d_in[8];
    const float* We    = (const float*)d_in[9];
    const float* be    = (const float*)d_in[10];
    const float* Wskip = (const float*)d_in[11];
    const float* bskip = (const float*)d_in[12];
    const float* ln_g  = (const float*)d_in[13];
    const float* ln_b  = (const float*)d_in[14];
    const float* Wlin  = (const float*)d_in[15];
    const float* blin  = (const float*)d_in[16];

    detect_kernel<<<1, 32>>>(ei);
    zero_kernel<<<(NN + 255) / 256, 256>>>();
    prep_kernel<<<STRD, 128>>>(Wq, bq, Wk, bk, Wv, bv, We, be, Wskip, bskip);

    dim3 g0((NN + 127) / 128, (STRD + 127) / 128);
    sgemm_kernel<0><<<g0, 256>>>(x, nullptr, nullptr, nullptr, nullptr);

    hist_kernel<<<(EE + 255) / 256, 256>>>(ei);
    scan_kernel<<<1, 1024>>>();
    fill_kernel<<<(EE + 255) / 256, 256>>>(ei);

    edge_alpha_kernel<<<(EE + 1) / 2, 256>>>(ea, ei);

    csr_agg_kernel<<<NN, 128>>>(ea);

    dim3 g4((NN + 127) / 128, HC / 128);
    sgemm_kernel<4><<<g4, 256>>>(nullptr, We, be, nullptr, nullptr);

    ln_kernel<<<NN, 128>>>(ln_g, ln_b);

    dim3 g5((NN + 127) / 128, 1);
    sgemm_kernel<5><<<g5, 256>>>(nullptr, Wlin, blin, x, (float*)d_out);
}

// round 6
// speedup vs baseline: 2.4855x; 1.0833x over previous
#include <cuda_runtime.h>
#include <math.h>
#include <stdint.h>

#define NN 10000
#define EE 160000
#define DD 128
#define HH 4
#define HC 512
#define STRD 2564            // fused node-feature stride: q|k|v|skip|qWe|qbe
#define QOFF 0
#define KOFF 512
#define VOFF 1024
#define SKOFF 1536
#define QWEOFF 2048
#define QBEOFF 2560
#define RSQRT_D 0.08838834764831845f  // 1/sqrt(128)
#define BPAD 136

// ---------------- scratch (device globals; no runtime allocation) -----------
__device__ float g_nodes[NN * STRD];   // fused per-node features
__device__ float g_Wcat[DD * STRD];    // concatenated weights
__device__ float g_bcat[STRD];         // concatenated bias
__device__ float g_ex[EE * HH];        // exp(alpha)
__device__ float g_aggv[NN * HC];      // sum attn * v[src]
__device__ float g_t[NN * HC];         // sum attn * edge_attr
__device__ float g_agge[NN * HC];      // t @ We (+ gated be)
__device__ float g_normed[NN * HC];
__device__ int   g_count[NN];
__device__ int   g_off[NN];
__device__ int   g_cur[NN];
__device__ int   g_elist[EE];
__device__ int   g_esrc[EE];
__device__ int   g_is64;

// ---- edge-index accessor: dtype decided at runtime, indices clamped --------
__device__ __forceinline__ int load_idx(const void* ei, int is64, long long pos) {
    int v = is64 ? (int)((const long long*)ei)[pos] : ((const int*)ei)[pos];
    return min(max(v, 0), NN - 1);
}

__global__ void detect_kernel(const void* ei) {
    if (threadIdx.x == 0 && blockIdx.x == 0) {
        const int* p = (const int*)ei;
        int orv = 0;
        for (int i = 1; i < 2048; i += 2) orv |= p[i];
        g_is64 = (orv == 0) ? 1 : 0;
    }
}

__global__ void zero_kernel() {
    int t = blockIdx.x * 256 + threadIdx.x;
    if (t < NN) g_count[t] = 0;
}

// ---------------- weight prep: build Wcat / bcat -----------------------------
__global__ __launch_bounds__(128) void prep_kernel(
    const float* __restrict__ Wq, const float* __restrict__ bq,
    const float* __restrict__ Wk, const float* __restrict__ bk,
    const float* __restrict__ Wv, const float* __restrict__ bv,
    const float* __restrict__ We, const float* __restrict__ be,
    const float* __restrict__ Wskip, const float* __restrict__ bskip) {
    int c = blockIdx.x, t = threadIdx.x;
    __shared__ float wrow[128];
    float val, bias = 0.f;
    if (c < 512)       { val = Wq[t * HC + c];            bias = bq[c]; }
    else if (c < 1024) { val = Wk[t * HC + c - 512];      bias = bk[c - 512]; }
    else if (c < 1536) { val = Wv[t * HC + c - 1024];     bias = bv[c - 1024]; }
    else if (c < 2048) { val = Wskip[t * HC + c - 1536];  bias = bskip[c - 1536]; }
    else if (c < 2560) {
        int cc = c - 2048, h = cc >> 7, m = cc & 127;
        wrow[t] = We[m * HC + h * 128 + t];
        __syncthreads();
        float acc = 0.f;
        for (int d = 0; d < 128; d++) acc += Wq[t * HC + h * 128 + d] * wrow[d];
        val = acc;
        if (t == 0) {
            float bacc = 0.f;
            for (int d = 0; d < 128; d++) bacc += bq[h * 128 + d] * wrow[d];
            bias = bacc;
        }
    } else {
        int h = c - 2560;
        float acc = 0.f;
        for (int d = 0; d < 128; d++) acc += Wq[t * HC + h * 128 + d] * be[h * 128 + d];
        val = acc;
        if (t == 0) {
            float bacc = 0.f;
            for (int d = 0; d < 128; d++) bacc += bq[h * 128 + d] * be[h * 128 + d];
            bias = bacc;
        }
    }
    g_Wcat[t * STRD + c] = val;
    if (t == 0) g_bcat[c] = bias;
}

// ---------------- tensor-core SGEMM (3xTF32, fp32-grade accuracy) ------------
// 128x128 tile, 256 thr, 8 warps (4M x 2N), warp tile 32x64, KT=16.
__device__ __forceinline__ uint32_t f2tf(float v) {
    uint32_t r;
    asm("cvt.rna.tf32.f32 %0, %1;" : "=r"(r) : "f"(v));
    return r;
}
__device__ __forceinline__ void mma8(float* c, const uint32_t* a, uint32_t b0, uint32_t b1) {
    asm volatile(
        "mma.sync.aligned.m16n8k8.row.col.f32.tf32.tf32.f32 "
        "{%0,%1,%2,%3}, {%4,%5,%6,%7}, {%8,%9}, {%0,%1,%2,%3};"
        : "+f"(c[0]), "+f"(c[1]), "+f"(c[2]), "+f"(c[3])
        : "r"(a[0]), "r"(a[1]), "r"(a[2]), "r"(a[3]), "r"(b0), "r"(b1));
}

// SEL 0: g_nodes = x @ Wcat + bcat        (K=128, N=2564)
// SEL 4: g_agge  = g_t(head) @ We + gated be (K=128, N=512, head = by)
// SEL 5: d_out   = elu(g_normed @ Wlin + blin + x) (K=512, N=128)
template <int SEL>
__global__ __launch_bounds__(256, 2) void sgemm_tc(
    const float* __restrict__ Ain, const float* __restrict__ Bin,
    const float* __restrict__ biasin, const float* __restrict__ xres,
    float* __restrict__ Cout) {
    constexpr int K    = (SEL == 5) ? 512 : 128;
    constexpr int NTOT = (SEL == 0) ? STRD : (SEL == 4) ? HC : DD;
    constexpr int BS   = NTOT;
    constexpr int ASTR = (SEL == 0) ? DD : HC;
    const float* A = (SEL == 0) ? Ain : (SEL == 4) ? g_t : g_normed;
    const float* B = (SEL == 0) ? g_Wcat : Bin;
    const float* bias_p = (SEL == 0) ? g_bcat : biasin;
    float* C = (SEL == 0) ? g_nodes : (SEL == 4) ? g_agge : Cout;

    __shared__ uint32_t sm[4 * 16 * BPAD];   // Ahi|Alo|Bhi|Blo; reused as stage
    uint32_t* sAhi = sm;
    uint32_t* sAlo = sm + 16 * BPAD;
    uint32_t* sBhi = sm + 2 * 16 * BPAD;
    uint32_t* sBlo = sm + 3 * 16 * BPAD;

    int tid = threadIdx.x;
    int lane = tid & 31, w = tid >> 5;
    int g = lane >> 2, tig = lane & 3;
    int wm = w & 3, wn = w >> 2;
    int m0 = wm * 32, n0 = wn * 64;
    int row0 = blockIdx.x * 128;
    int col0 = blockIdx.y * 128;
    const int acb = (SEL == 4) ? col0 : 0;

    float acc[2][8][4];
#pragma unroll
    for (int mt = 0; mt < 2; mt++)
#pragma unroll
        for (int nt = 0; nt < 8; nt++)
#pragma unroll
            for (int r = 0; r < 4; r++) acc[mt][nt][r] = 0.f;

    for (int kb = 0; kb < K; kb += 16) {
        __syncthreads();
        // ---- load A tile (k-major, swizzled, split hi/lo) ----
#pragma unroll
        for (int i = 0; i < 2; i++) {
            int qi = tid + i * 256;
            int m = qi >> 2, kq = qi & 3;
            int r = row0 + m;
            float4 av = make_float4(0.f, 0.f, 0.f, 0.f);
            if (r < NN) av = *(const float4*)&A[(size_t)r * ASTR + acb + kb + kq * 4];
            float vv[4] = {av.x, av.y, av.z, av.w};
#pragma unroll
            for (int j = 0; j < 4; j++) {
                int kk = kq * 4 + j;
                uint32_t hi = f2tf(vv[j]);
                float lo = vv[j] - __uint_as_float(hi);
                int idx = kk * BPAD + (m ^ ((kk >> 2) << 3));
                sAhi[idx] = hi;
                sAlo[idx] = f2tf(lo);
            }
        }
        // ---- load B tile (split hi/lo) ----
#pragma unroll
        for (int i = 0; i < 2; i++) {
            int qi = tid + i * 256;
            int kk = qi >> 5, nq = qi & 31;
            int c = col0 + nq * 4;
            float4 bv = make_float4(0.f, 0.f, 0.f, 0.f);
            if (c + 4 <= NTOT) bv = *(const float4*)&B[(size_t)(kb + kk) * BS + c];
            float vv[4] = {bv.x, bv.y, bv.z, bv.w};
#pragma unroll
            for (int j = 0; j < 4; j++) {
                uint32_t hi = f2tf(vv[j]);
                float lo = vv[j] - __uint_as_float(hi);
                sBhi[kk * BPAD + nq * 4 + j] = hi;
                sBlo[kk * BPAD + nq * 4 + j] = f2tf(lo);
            }
        }
        __syncthreads();
        // ---- 2 k-steps of 8 ----
#pragma unroll
        for (int ks = 0; ks < 2; ks++) {
            int rlo = ks * 8 + tig, rhi = ks * 8 + tig + 4;
            int s1 = (rlo >> 2) << 3, s2 = (rhi >> 2) << 3;
            uint32_t ahi[2][4], alo[2][4];
#pragma unroll
            for (int mt = 0; mt < 2; mt++) {
                int mb = m0 + mt * 16 + g;
                ahi[mt][0] = sAhi[rlo * BPAD + (mb ^ s1)];
                ahi[mt][1] = sAhi[rlo * BPAD + ((mb + 8) ^ s1)];
                ahi[mt][2] = sAhi[rhi * BPAD + (mb ^ s2)];
                ahi[mt][3] = sAhi[rhi * BPAD + ((mb + 8) ^ s2)];
                alo[mt][0] = sAlo[rlo * BPAD + (mb ^ s1)];
                alo[mt][1] = sAlo[rlo * BPAD + ((mb + 8) ^ s1)];
                alo[mt][2] = sAlo[rhi * BPAD + (mb ^ s2)];
                alo[mt][3] = sAlo[rhi * BPAD + ((mb + 8) ^ s2)];
            }
#pragma unroll
            for (int nt = 0; nt < 8; nt++) {
                int nb = n0 + nt * 8 + g;
                uint32_t bh0 = sBhi[rlo * BPAD + nb];
                uint32_t bh1 = sBhi[rhi * BPAD + nb];
                uint32_t bl0 = sBlo[rlo * BPAD + nb];
                uint32_t bl1 = sBlo[rhi * BPAD + nb];
#pragma unroll
                for (int mt = 0; mt < 2; mt++) {
                    mma8(acc[mt][nt], ahi[mt], bl0, bl1);  // hi*lo
                    mma8(acc[mt][nt], alo[mt], bh0, bh1);  // lo*hi
                    mma8(acc[mt][nt], ahi[mt], bh0, bh1);  // hi*hi
                }
            }
        }
    }

    // ---- epilogue: stage via smem for coalesced stores ----
    float* stg = (float*)sm;   // 128 x 68
#pragma unroll
    for (int p = 0; p < 2; p++) {
        __syncthreads();
        if (wn == p) {
#pragma unroll
            for (int mt = 0; mt < 2; mt++)
#pragma unroll
                for (int nt = 0; nt < 8; nt++) {
                    int rl = m0 + mt * 16 + g;
                    int cl = nt * 8 + tig * 2;
                    stg[rl * 68 + cl]           = acc[mt][nt][0];
                    stg[rl * 68 + cl + 1]       = acc[mt][nt][1];
                    stg[(rl + 8) * 68 + cl]     = acc[mt][nt][2];
                    stg[(rl + 8) * 68 + cl + 1] = acc[mt][nt][3];
                }
        }
        __syncthreads();
#pragma unroll
        for (int i = 0; i < 8; i++) {
            int qi = tid + i * 256;
            int rl = qi >> 4, q4 = qi & 15;
            int grow = row0 + rl;
            int gcol = col0 + p * 64 + q4 * 4;
            if (grow < NN && gcol + 4 <= NTOT) {
                float4 v = *(float4*)&stg[rl * 68 + q4 * 4];
                float gate = 1.f;
                if (SEL == 4) gate = (g_count[grow] > 0) ? 1.f : 0.f;
                float o[4] = {v.x, v.y, v.z, v.w};
#pragma unroll
                for (int j = 0; j < 4; j++) {
                    o[j] += gate * bias_p[gcol + j];
                    if (SEL == 5) {
                        o[j] += xres[(size_t)grow * DD + gcol + j];
                        o[j] = (o[j] > 0.f) ? o[j] : expm1f(o[j]);
                    }
                }
                *(float4*)&C[(size_t)grow * BS + gcol] = make_float4(o[0], o[1], o[2], o[3]);
            }
        }
    }
}

// ---------------- CSR build (int atomics only, in-bounds by clamp) -----------
__global__ void hist_kernel(const void* __restrict__ ei) {
    int t = blockIdx.x * 256 + threadIdx.x;
    if (t < EE) {
        int d = load_idx(ei, g_is64, (long long)EE + t);
        atomicAdd(&g_count[d], 1);
    }
}

__global__ __launch_bounds__(1024) void scan_kernel() {
    __shared__ int sh[1024];
    int t = threadIdx.x;
    int loc[16];
    int s = 0;
#pragma unroll
    for (int i = 0; i < 16; i++) {
        int idx = t * 16 + i;
        int cv = (idx < NN) ? g_count[idx] : 0;
        loc[i] = cv; s += cv;
    }
    sh[t] = s;
    __syncthreads();
    for (int off = 1; off < 1024; off <<= 1) {
        int v = (t >= off) ? sh[t - off] : 0;
        __syncthreads();
        sh[t] += v;
        __syncthreads();
    }
    int excl = sh[t] - s;
#pragma unroll
    for (int i = 0; i < 16; i++) {
        int idx = t * 16 + i;
        if (idx < NN) {
            g_off[idx] = excl;
            g_cur[idx] = excl;
            excl += loc[i];
        }
    }
}

__global__ void fill_kernel(const void* __restrict__ ei) {
    int t = blockIdx.x * 256 + threadIdx.x;
    if (t < EE) {
        int is64 = g_is64;
        int d = load_idx(ei, is64, (long long)EE + t);
        int pos = atomicAdd(&g_cur[d], 1);
        pos = min(max(pos, 0), EE - 1);
        g_elist[pos] = t;
        g_esrc[pos]  = load_idx(ei, is64, t);
    }
}

// ---------------- edge pass: alpha -> exp (no atomics) -----------------------
__global__ __launch_bounds__(256) void edge_alpha_kernel(
    const float* __restrict__ ea, const void* __restrict__ ei) {
    __shared__ float red[8][4];
    int tid = threadIdx.x;
    int e = blockIdx.x * 2 + (tid >> 7);
    int l = tid & 127;
    int w = tid >> 5;
    int is64 = g_is64;

    float p[4] = {0.f, 0.f, 0.f, 0.f};
    if (e < EE) {
        int s = load_idx(ei, is64, e);
        int d = load_idx(ei, is64, (long long)EE + e);
        float eav = ea[e * DD + l];
#pragma unroll
        for (int h = 0; h < 4; h++) {
            int o = h * 128 + l;
            p[h] = g_nodes[d * STRD + QOFF + o] * g_nodes[s * STRD + KOFF + o]
                 + eav * g_nodes[d * STRD + QWEOFF + o];
        }
    }
#pragma unroll
    for (int h = 0; h < 4; h++) {
#pragma unroll
        for (int off = 16; off > 0; off >>= 1)
            p[h] += __shfl_xor_sync(0xffffffffu, p[h], off);
    }
    if ((tid & 31) == 0) {
#pragma unroll
        for (int h = 0; h < 4; h++) red[w][h] = p[h];
    }
    __syncthreads();
    if (tid < 8) {
        int slot = tid >> 2, h = tid & 3;
        int e2 = blockIdx.x * 2 + slot;
        if (e2 < EE) {
            float a = red[slot * 4 + 0][h] + red[slot * 4 + 1][h]
                    + red[slot * 4 + 2][h] + red[slot * 4 + 3][h];
            int d2 = load_idx(ei, is64, (long long)EE + e2);
            a = (a + g_nodes[d2 * STRD + QBEOFF + h]) * RSQRT_D;
            g_ex[e2 * HH + h] = expf(a);
        }
    }
}

// ---------------- CSR aggregate: block per dst node, denom inline ------------
__global__ __launch_bounds__(128) void csr_agg_kernel(const float* __restrict__ ea) {
    int n = blockIdx.x;
    int l = threadIdx.x;
    int off = g_off[n];
    int cnt = g_count[n];

    float accv[4] = {0.f, 0.f, 0.f, 0.f};
    float acct[4] = {0.f, 0.f, 0.f, 0.f};

    if (cnt > 0) {
        float den[4] = {0.f, 0.f, 0.f, 0.f};
        for (int k = 0; k < cnt; k++) {
            int eid = g_elist[off + k];
#pragma unroll
            for (int h = 0; h < 4; h++) den[h] += g_ex[eid * HH + h];
        }
        float rden[4];
#pragma unroll
        for (int h = 0; h < 4; h++) rden[h] = 1.f / den[h];

        for (int k = 0; k < cnt; k++) {
            int eid = g_elist[off + k];
            int s   = g_esrc[off + k];
            float eav = ea[eid * DD + l];
#pragma unroll
            for (int h = 0; h < 4; h++) {
                float at = g_ex[eid * HH + h] * rden[h];
                accv[h] += at * g_nodes[s * STRD + VOFF + h * 128 + l];
                acct[h] += at * eav;
            }
        }
    }
#pragma unroll
    for (int h = 0; h < 4; h++) {
        g_aggv[n * HC + h * 128 + l] = accv[h];
        g_t[n * HC + h * 128 + l]   = acct[h];
    }
}

// ---------------- LayerNorm over HC=512 (aggv + agge + skip) -----------------
__global__ __launch_bounds__(128) void ln_kernel(
    const float* __restrict__ g, const float* __restrict__ b) {
    int n = blockIdx.x;
    int tid = threadIdx.x;
    float vals[4];
    float s = 0.f, s2 = 0.f;
#pragma unroll
    for (int j = 0; j < 4; j++) {
        int c = tid + j * 128;
        float o = g_aggv[n * HC + c] + g_agge[n * HC + c]
                + g_nodes[n * STRD + SKOFF + c];
        vals[j] = o; s += o; s2 += o * o;
    }
    __shared__ float sh[8];
#pragma unroll
    for (int off = 16; off > 0; off >>= 1) {
        s  += __shfl_xor_sync(0xffffffffu, s, off);
        s2 += __shfl_xor_sync(0xffffffffu, s2, off);
    }
    int wid = tid >> 5, lane = tid & 31;
    if (lane == 0) { sh[wid] = s; sh[4 + wid] = s2; }
    __syncthreads();
    s  = sh[0] + sh[1] + sh[2] + sh[3];
    s2 = sh[4] + sh[5] + sh[6] + sh[7];
    float mu = s * (1.f / 512.f);
    float var = s2 * (1.f / 512.f) - mu * mu;
    float rs = rsqrtf(var + 1e-5f);
#pragma unroll
    for (int j = 0; j < 4; j++) {
        int c = tid + j * 128;
        g_normed[n * HC + c] = (vals[j] - mu) * rs * g[c] + b[c];
    }
}

// ---------------- launch -----------------------------------------------------
extern "C" void kernel_launch(void* const* d_in, const int* in_sizes, int n_in,
                              void* d_out, int out_size) {
    const float* x     = (const float*)d_in[0];
    const void*  ei    = d_in[1];
    const float* ea    = (const float*)d_in[2];
    const float* Wq    = (const float*)d_in[3];
    const float* bq    = (const float*)d_in[4];
    const float* Wk    = (const float*)d_in[5];
    const float* bk    = (const float*)d_in[6];
    const float* Wv    = (const float*)d_in[7];
    const float* bv    = (const float*)d_in[8];
    const float* We    = (const float*)d_in[9];
    const float* be    = (const float*)d_in[10];
    const float* Wskip = (const float*)d_in[11];
    const float* bskip = (const float*)d_in[12];
    const float* ln_g  = (const float*)d_in[13];
    const float* ln_b  = (const float*)d_in[14];
    const float* Wlin  = (const float*)d_in[15];
    const float* blin  = (const float*)d_in[16];

    detect_kernel<<<1, 32>>>(ei);
    zero_kernel<<<(NN + 255) / 256, 256>>>();
    prep_kernel<<<STRD, 128>>>(Wq, bq, Wk, bk, Wv, bv, We, be, Wskip, bskip);

    dim3 g0((NN + 127) / 128, (STRD + 127) / 128);
    sgemm_tc<0><<<g0, 256>>>(x, nullptr, nullptr, nullptr, nullptr);

    hist_kernel<<<(EE + 255) / 256, 256>>>(ei);
    scan_kernel<<<1, 1024>>>();
    fill_kernel<<<(EE + 255) / 256, 256>>>(ei);

    edge_alpha_kernel<<<(EE + 1) / 2, 256>>>(ea, ei);

    csr_agg_kernel<<<NN, 128>>>(ea);

    dim3 g4((NN + 127) / 128, HC / 128);
    sgemm_tc<4><<<g4, 256>>>(nullptr, We, be, nullptr, nullptr);

    ln_kernel<<<NN, 128>>>(ln_g, ln_b);

    dim3 g5((NN + 127) / 128, 1);
    sgemm_tc<5><<<g5, 256>>>(nullptr, Wlin, blin, x, (float*)d_out);
}

// round 7
// speedup vs baseline: 2.9265x; 1.1774x over previous
#include <cuda_runtime.h>
#include <math.h>
#include <stdint.h>

#define NN 10000
#define EE 160000
#define DD 128
#define HH 4
#define HC 512
#define STRD 2564            // fused node-feature stride: q|k|v|skip|qWe|qbe
#define QOFF 0
#define KOFF 512
#define VOFF 1024
#define SKOFF 1536
#define QWEOFF 2048
#define QBEOFF 2560
#define RSQRT_D 0.08838834764831845f  // 1/sqrt(128)
#define BPAD 136

// ---------------- scratch (device globals; no runtime allocation) -----------
__device__ float g_nodes[NN * STRD];   // fused per-node features
__device__ float g_Wcat[DD * STRD];    // concatenated weights
__device__ float g_bcat[STRD];         // concatenated bias
__device__ float g_aggv[NN * HC];      // softmax-weighted v aggregate
__device__ float g_t[NN * HC];         // softmax-weighted edge_attr aggregate
__device__ float g_agge[NN * HC];      // t @ We (+ gated be)
__device__ float g_normed[NN * HC];
__device__ int   g_count[NN];
__device__ int   g_off[NN];
__device__ int   g_cur[NN];
__device__ int   g_elist[EE];
__device__ int   g_esrc[EE];
__device__ int   g_is64;

// ---- edge-index accessor: dtype decided at runtime, indices clamped --------
__device__ __forceinline__ int load_idx(const void* ei, int is64, long long pos) {
    int v = is64 ? (int)((const long long*)ei)[pos] : ((const int*)ei)[pos];
    return min(max(v, 0), NN - 1);
}

__global__ void detect_kernel(const void* ei) {
    if (threadIdx.x == 0 && blockIdx.x == 0) {
        const int* p = (const int*)ei;
        int orv = 0;
        for (int i = 1; i < 2048; i += 2) orv |= p[i];
        g_is64 = (orv == 0) ? 1 : 0;
    }
}

__global__ void zero_kernel() {
    int t = blockIdx.x * 256 + threadIdx.x;
    if (t < NN) g_count[t] = 0;
}

// ---------------- weight prep: build Wcat / bcat -----------------------------
__global__ __launch_bounds__(128) void prep_kernel(
    const float* __restrict__ Wq, const float* __restrict__ bq,
    const float* __restrict__ Wk, const float* __restrict__ bk,
    const float* __restrict__ Wv, const float* __restrict__ bv,
    const float* __restrict__ We, const float* __restrict__ be,
    const float* __restrict__ Wskip, const float* __restrict__ bskip) {
    int c = blockIdx.x, t = threadIdx.x;
    __shared__ float wrow[128];
    float val, bias = 0.f;
    if (c < 512)       { val = Wq[t * HC + c];            bias = bq[c]; }
    else if (c < 1024) { val = Wk[t * HC + c - 512];      bias = bk[c - 512]; }
    else if (c < 1536) { val = Wv[t * HC + c - 1024];     bias = bv[c - 1024]; }
    else if (c < 2048) { val = Wskip[t * HC + c - 1536];  bias = bskip[c - 1536]; }
    else if (c < 2560) {
        int cc = c - 2048, h = cc >> 7, m = cc & 127;
        wrow[t] = We[m * HC + h * 128 + t];
        __syncthreads();
        float acc = 0.f;
        for (int d = 0; d < 128; d++) acc += Wq[t * HC + h * 128 + d] * wrow[d];
        val = acc;
        if (t == 0) {
            float bacc = 0.f;
            for (int d = 0; d < 128; d++) bacc += bq[h * 128 + d] * wrow[d];
            bias = bacc;
        }
    } else {
        int h = c - 2560;
        float acc = 0.f;
        for (int d = 0; d < 128; d++) acc += Wq[t * HC + h * 128 + d] * be[h * 128 + d];
        val = acc;
        if (t == 0) {
            float bacc = 0.f;
            for (int d = 0; d < 128; d++) bacc += bq[h * 128 + d] * be[h * 128 + d];
            bias = bacc;
        }
    }
    g_Wcat[t * STRD + c] = val;
    if (t == 0) g_bcat[c] = bias;
}

// ---------------- tensor-core SGEMM (3xTF32, fp32-grade accuracy) ------------
__device__ __forceinline__ uint32_t f2tf(float v) {
    uint32_t r;
    asm("cvt.rna.tf32.f32 %0, %1;" : "=r"(r) : "f"(v));
    return r;
}
__device__ __forceinline__ void mma8(float* c, const uint32_t* a, uint32_t b0, uint32_t b1) {
    asm volatile(
        "mma.sync.aligned.m16n8k8.row.col.f32.tf32.tf32.f32 "
        "{%0,%1,%2,%3}, {%4,%5,%6,%7}, {%8,%9}, {%0,%1,%2,%3};"
        : "+f"(c[0]), "+f"(c[1]), "+f"(c[2]), "+f"(c[3])
        : "r"(a[0]), "r"(a[1]), "r"(a[2]), "r"(a[3]), "r"(b0), "r"(b1));
}

// SEL 0: g_nodes = x @ Wcat + bcat           (K=128, N=2564)
// SEL 4: g_agge  = g_t(head) @ We + gated be (K=128, N=512, head = by)
// SEL 5: d_out   = elu(g_normed @ Wlin + blin + x) (K=512, N=128)
template <int SEL>
__global__ __launch_bounds__(256, 2) void sgemm_tc(
    const float* __restrict__ Ain, const float* __restrict__ Bin,
    const float* __restrict__ biasin, const float* __restrict__ xres,
    float* __restrict__ Cout) {
    constexpr int K    = (SEL == 5) ? 512 : 128;
    constexpr int NTOT = (SEL == 0) ? STRD : (SEL == 4) ? HC : DD;
    constexpr int BS   = NTOT;
    constexpr int ASTR = (SEL == 0) ? DD : HC;
    const float* A = (SEL == 0) ? Ain : (SEL == 4) ? g_t : g_normed;
    const float* B = (SEL == 0) ? g_Wcat : Bin;
    const float* bias_p = (SEL == 0) ? g_bcat : biasin;
    float* C = (SEL == 0) ? g_nodes : (SEL == 4) ? g_agge : Cout;

    __shared__ uint32_t sm[4 * 16 * BPAD];   // Ahi|Alo|Bhi|Blo; reused as stage
    uint32_t* sAhi = sm;
    uint32_t* sAlo = sm + 16 * BPAD;
    uint32_t* sBhi = sm + 2 * 16 * BPAD;
    uint32_t* sBlo = sm + 3 * 16 * BPAD;

    int tid = threadIdx.x;
    int lane = tid & 31, w = tid >> 5;
    int g = lane >> 2, tig = lane & 3;
    int wm = w & 3, wn = w >> 2;
    int m0 = wm * 32, n0 = wn * 64;
    int row0 = blockIdx.x * 128;
    int col0 = blockIdx.y * 128;
    const int acb = (SEL == 4) ? col0 : 0;

    float acc[2][8][4];
#pragma unroll
    for (int mt = 0; mt < 2; mt++)
#pragma unroll
        for (int nt = 0; nt < 8; nt++)
#pragma unroll
            for (int r = 0; r < 4; r++) acc[mt][nt][r] = 0.f;

    for (int kb = 0; kb < K; kb += 16) {
        __syncthreads();
#pragma unroll
        for (int i = 0; i < 2; i++) {
            int qi = tid + i * 256;
            int m = qi >> 2, kq = qi & 3;
            int r = row0 + m;
            float4 av = make_float4(0.f, 0.f, 0.f, 0.f);
            if (r < NN) av = *(const float4*)&A[(size_t)r * ASTR + acb + kb + kq * 4];
            float vv[4] = {av.x, av.y, av.z, av.w};
#pragma unroll
            for (int j = 0; j < 4; j++) {
                int kk = kq * 4 + j;
                uint32_t hi = f2tf(vv[j]);
                float lo = vv[j] - __uint_as_float(hi);
                int idx = kk * BPAD + (m ^ ((kk >> 2) << 3));
                sAhi[idx] = hi;
                sAlo[idx] = f2tf(lo);
            }
        }
#pragma unroll
        for (int i = 0; i < 2; i++) {
            int qi = tid + i * 256;
            int kk = qi >> 5, nq = qi & 31;
            int c = col0 + nq * 4;
            float4 bv = make_float4(0.f, 0.f, 0.f, 0.f);
            if (c + 4 <= NTOT) bv = *(const float4*)&B[(size_t)(kb + kk) * BS + c];
            float vv[4] = {bv.x, bv.y, bv.z, bv.w};
#pragma unroll
            for (int j = 0; j < 4; j++) {
                uint32_t hi = f2tf(vv[j]);
                float lo = vv[j] - __uint_as_float(hi);
                sBhi[kk * BPAD + nq * 4 + j] = hi;
                sBlo[kk * BPAD + nq * 4 + j] = f2tf(lo);
            }
        }
        __syncthreads();
#pragma unroll
        for (int ks = 0; ks < 2; ks++) {
            int rlo = ks * 8 + tig, rhi = ks * 8 + tig + 4;
            int s1 = (rlo >> 2) << 3, s2 = (rhi >> 2) << 3;
            uint32_t ahi[2][4], alo[2][4];
#pragma unroll
            for (int mt = 0; mt < 2; mt++) {
                int mb = m0 + mt * 16 + g;
                ahi[mt][0] = sAhi[rlo * BPAD + (mb ^ s1)];
                ahi[mt][1] = sAhi[rlo * BPAD + ((mb + 8) ^ s1)];
                ahi[mt][2] = sAhi[rhi * BPAD + (mb ^ s2)];
                ahi[mt][3] = sAhi[rhi * BPAD + ((mb + 8) ^ s2)];
                alo[mt][0] = sAlo[rlo * BPAD + (mb ^ s1)];
                alo[mt][1] = sAlo[rlo * BPAD + ((mb + 8) ^ s1)];
                alo[mt][2] = sAlo[rhi * BPAD + (mb ^ s2)];
                alo[mt][3] = sAlo[rhi * BPAD + ((mb + 8) ^ s2)];
            }
#pragma unroll
            for (int nt = 0; nt < 8; nt++) {
                int nb = n0 + nt * 8 + g;
                uint32_t bh0 = sBhi[rlo * BPAD + nb];
                uint32_t bh1 = sBhi[rhi * BPAD + nb];
                uint32_t bl0 = sBlo[rlo * BPAD + nb];
                uint32_t bl1 = sBlo[rhi * BPAD + nb];
#pragma unroll
                for (int mt = 0; mt < 2; mt++) {
                    mma8(acc[mt][nt], ahi[mt], bl0, bl1);
                    mma8(acc[mt][nt], alo[mt], bh0, bh1);
                    mma8(acc[mt][nt], ahi[mt], bh0, bh1);
                }
            }
        }
    }

    float* stg = (float*)sm;   // 128 x 68
#pragma unroll
    for (int p = 0; p < 2; p++) {
        __syncthreads();
        if (wn == p) {
#pragma unroll
            for (int mt = 0; mt < 2; mt++)
#pragma unroll
                for (int nt = 0; nt < 8; nt++) {
                    int rl = m0 + mt * 16 + g;
                    int cl = nt * 8 + tig * 2;
                    stg[rl * 68 + cl]           = acc[mt][nt][0];
                    stg[rl * 68 + cl + 1]       = acc[mt][nt][1];
                    stg[(rl + 8) * 68 + cl]     = acc[mt][nt][2];
                    stg[(rl + 8) * 68 + cl + 1] = acc[mt][nt][3];
                }
        }
        __syncthreads();
#pragma unroll
        for (int i = 0; i < 8; i++) {
            int qi = tid + i * 256;
            int rl = qi >> 4, q4 = qi & 15;
            int grow = row0 + rl;
            int gcol = col0 + p * 64 + q4 * 4;
            if (grow < NN && gcol + 4 <= NTOT) {
                float4 v = *(float4*)&stg[rl * 68 + q4 * 4];
                float gate = 1.f;
                if (SEL == 4) gate = (g_count[grow] > 0) ? 1.f : 0.f;
                float o[4] = {v.x, v.y, v.z, v.w};
#pragma unroll
                for (int j = 0; j < 4; j++) {
                    o[j] += gate * bias_p[gcol + j];
                    if (SEL == 5) {
                        o[j] += xres[(size_t)grow * DD + gcol + j];
                        o[j] = (o[j] > 0.f) ? o[j] : expm1f(o[j]);
                    }
                }
                *(float4*)&C[(size_t)grow * BS + gcol] = make_float4(o[0], o[1], o[2], o[3]);
            }
        }
    }
}

// ---------------- CSR build (int atomics only, in-bounds by clamp) -----------
__global__ void hist_kernel(const void* __restrict__ ei) {
    int t = blockIdx.x * 256 + threadIdx.x;
    if (t < EE) {
        int d = load_idx(ei, g_is64, (long long)EE + t);
        atomicAdd(&g_count[d], 1);
    }
}

__global__ __launch_bounds__(1024) void scan_kernel() {
    __shared__ int sh[1024];
    int t = threadIdx.x;
    int loc[16];
    int s = 0;
#pragma unroll
    for (int i = 0; i < 16; i++) {
        int idx = t * 16 + i;
        int cv = (idx < NN) ? g_count[idx] : 0;
        loc[i] = cv; s += cv;
    }
    sh[t] = s;
    __syncthreads();
    for (int off = 1; off < 1024; off <<= 1) {
        int v = (t >= off) ? sh[t - off] : 0;
        __syncthreads();
        sh[t] += v;
        __syncthreads();
    }
    int excl = sh[t] - s;
#pragma unroll
    for (int i = 0; i < 16; i++) {
        int idx = t * 16 + i;
        if (idx < NN) {
            g_off[idx] = excl;
            g_cur[idx] = excl;
            excl += loc[i];
        }
    }
}

__global__ void fill_kernel(const void* __restrict__ ei) {
    int t = blockIdx.x * 256 + threadIdx.x;
    if (t < EE) {
        int is64 = g_is64;
        int d = load_idx(ei, is64, (long long)EE + t);
        int pos = atomicAdd(&g_cur[d], 1);
        pos = min(max(pos, 0), EE - 1);
        g_elist[pos] = t;
        g_esrc[pos]  = load_idx(ei, is64, t);
    }
}

// ---------------- fused edge pass: alpha + softmax + aggregation -------------
// One block per dst node. Denominator is factored out: accumulate unnormalized
// sums of ex*v and ex*ea, scale by 1/den at the end (identical math).
// 4 warps each compute one edge's alpha concurrently (intra-warp shfl reduce),
// then all 128 lanes accumulate the 4 edges' weighted v / edge_attr.
__global__ __launch_bounds__(128) void agg_fused_kernel(const float* __restrict__ ea) {
    int n = blockIdx.x;
    int l = threadIdx.x;          // 0..127
    int lane = l & 31, w = l >> 5;
    int off = g_off[n], cnt = g_count[n];

    __shared__ float sq[HC], sqw[HC];
    __shared__ float sex[4][4];   // [edge slot][head]
    __shared__ int   ss[4], se[4];

#pragma unroll
    for (int h = 0; h < 4; h++) {
        sq[h * 128 + l]  = g_nodes[(size_t)n * STRD + QOFF + h * 128 + l];
        sqw[h * 128 + l] = g_nodes[(size_t)n * STRD + QWEOFF + h * 128 + l];
    }
    __syncthreads();

    float den[4]  = {0.f, 0.f, 0.f, 0.f};
    float accv[4] = {0.f, 0.f, 0.f, 0.f};
    float acct[4] = {0.f, 0.f, 0.f, 0.f};

    for (int k0 = 0; k0 < cnt; k0 += 4) {
        int myk = k0 + w;
        if (myk < cnt) {
            int s   = g_esrc[off + myk];
            int eid = g_elist[off + myk];
            if (lane == 0) { ss[w] = s; se[w] = eid; }
            float p[4] = {0.f, 0.f, 0.f, 0.f};
#pragma unroll
            for (int c = 0; c < 4; c++) {
                int db = c * 32 + lane;
                float eav = __ldg(&ea[(size_t)eid * DD + db]);
#pragma unroll
                for (int h = 0; h < 4; h++) {
                    int o = h * 128 + db;
                    p[h] += sq[o] * __ldg(&g_nodes[(size_t)s * STRD + KOFF + o])
                          + eav * sqw[o];
                }
            }
#pragma unroll
            for (int offs = 16; offs > 0; offs >>= 1) {
#pragma unroll
                for (int h = 0; h < 4; h++)
                    p[h] += __shfl_xor_sync(0xffffffffu, p[h], offs);
            }
            if (lane == 0) {
#pragma unroll
                for (int h = 0; h < 4; h++) {
                    float a = (p[h] + g_nodes[(size_t)n * STRD + QBEOFF + h]) * RSQRT_D;
                    sex[w][h] = expf(a);
                }
            }
        }
        __syncthreads();
        int jmax = min(4, cnt - k0);
        for (int j = 0; j < jmax; j++) {
            int sj = ss[j], ej = se[j];
            float eav = __ldg(&ea[(size_t)ej * DD + l]);
#pragma unroll
            for (int h = 0; h < 4; h++) {
                float ex = sex[j][h];
                den[h]  += ex;
                accv[h] += ex * __ldg(&g_nodes[(size_t)sj * STRD + VOFF + h * 128 + l]);
                acct[h] += ex * eav;
            }
        }
        __syncthreads();
    }

#pragma unroll
    for (int h = 0; h < 4; h++) {
        float rd = (cnt > 0) ? 1.f / den[h] : 0.f;
        g_aggv[(size_t)n * HC + h * 128 + l] = accv[h] * rd;
        g_t[(size_t)n * HC + h * 128 + l]    = acct[h] * rd;
    }
}

// ---------------- LayerNorm over HC=512 (aggv + agge + skip) -----------------
__global__ __launch_bounds__(128) void ln_kernel(
    const float* __restrict__ g, const float* __restrict__ b) {
    int n = blockIdx.x;
    int tid = threadIdx.x;
    float vals[4];
    float s = 0.f, s2 = 0.f;
#pragma unroll
    for (int j = 0; j < 4; j++) {
        int c = tid + j * 128;
        float o = g_aggv[(size_t)n * HC + c] + g_agge[(size_t)n * HC + c]
                + g_nodes[(size_t)n * STRD + SKOFF + c];
        vals[j] = o; s += o; s2 += o * o;
    }
    __shared__ float sh[8];
#pragma unroll
    for (int off = 16; off > 0; off >>= 1) {
        s  += __shfl_xor_sync(0xffffffffu, s, off);
        s2 += __shfl_xor_sync(0xffffffffu, s2, off);
    }
    int wid = tid >> 5, lane = tid & 31;
    if (lane == 0) { sh[wid] = s; sh[4 + wid] = s2; }
    __syncthreads();
    s  = sh[0] + sh[1] + sh[2] + sh[3];
    s2 = sh[4] + sh[5] + sh[6] + sh[7];
    float mu = s * (1.f / 512.f);
    float var = s2 * (1.f / 512.f) - mu * mu;
    float rs = rsqrtf(var + 1e-5f);
#pragma unroll
    for (int j = 0; j < 4; j++) {
        int c = tid + j * 128;
        g_normed[(size_t)n * HC + c] = (vals[j] - mu) * rs * g[c] + b[c];
    }
}

// ---------------- launch -----------------------------------------------------
extern "C" void kernel_launch(void* const* d_in, const int* in_sizes, int n_in,
                              void* d_out, int out_size) {
    const float* x     = (const float*)d_in[0];
    const void*  ei    = d_in[1];
    const float* ea    = (const float*)d_in[2];
    const float* Wq    = (const float*)d_in[3];
    const float* bq    = (const float*)d_in[4];
    const float* Wk    = (const float*)d_in[5];
    const float* bk    = (const float*)d_in[6];
    const float* Wv    = (const float*)d_in[7];
    const float* bv    = (const float*)d_in[8];
    const float* We    = (const float*)d_in[9];
    const float* be    = (const float*)d_in[10];
    const float* Wskip = (const float*)d_in[11];
    const float* bskip = (const float*)d_in[12];
    const float* ln_g  = (const float*)d_in[13];
    const float* ln_b  = (const float*)d_in[14];
    const float* Wlin  = (const float*)d_in[15];
    const float* blin  = (const float*)d_in[16];

    detect_kernel<<<1, 32>>>(ei);
    zero_kernel<<<(NN + 255) / 256, 256>>>();
    prep_kernel<<<STRD, 128>>>(Wq, bq, Wk, bk, Wv, bv, We, be, Wskip, bskip);

    dim3 g0((NN + 127) / 128, (STRD + 127) / 128);
    sgemm_tc<0><<<g0, 256>>>(x, nullptr, nullptr, nullptr, nullptr);

    hist_kernel<<<(EE + 255) / 256, 256>>>(ei);
    scan_kernel<<<1, 1024>>>();
    fill_kernel<<<(EE + 255) / 256, 256>>>(ei);

    agg_fused_kernel<<<NN, 128>>>(ea);

    dim3 g4((NN + 127) / 128, HC / 128);
    sgemm_tc<4><<<g4, 256>>>(nullptr, We, be, nullptr, nullptr);

    ln_kernel<<<NN, 128>>>(ln_g, ln_b);

    dim3 g5((NN + 127) / 128, 1);
    sgemm_tc<5><<<g5, 256>>>(nullptr, Wlin, blin, x, (float*)d_out);
}